// round 1
// baseline (speedup 1.0000x reference)
#include <cuda_runtime.h>
#include <cuda_fp16.h>
#include <cstdint>

#define NB 4096   // tokens
#define NH 1024   // hidden
#define ND 4096   // expert dim
#define NE 8      // experts

// ---------------- scratch (__device__ globals: allocation-guard safe) ----------------
__device__ __half g_xh [(size_t)NB * NH];          //  8 MB  x in fp16
__device__ __half g_w1h[(size_t)NE * NH * ND];     // 64 MB  w1 fp16
__device__ __half g_w2h[(size_t)NE * ND * NH];     // 64 MB  w2 fp16
__device__ __half g_h  [(size_t)NE * NB * ND];     // 256 MB h scratch (per-expert slots)
__device__ int    g_cnt[NE];
__device__ int    g_idx[NE * NB];
__device__ float  g_scale[NE * NB];
__device__ float  g_psum[NE];
__device__ float  g_rsum[NE];

// ---------------- helpers ----------------
__device__ __forceinline__ uint32_t smem_u32(const void* p) {
    return (uint32_t)__cvta_generic_to_shared(p);
}
__device__ __forceinline__ void cp16(const void* smem, const void* gmem) {
    asm volatile("cp.async.cg.shared.global [%0], [%1], 16;\n"
                 :: "r"(smem_u32(smem)), "l"(gmem) : "memory");
}

// ---------------- init: zero y + counters ----------------
__global__ void init_kernel(float* __restrict__ y) {
    size_t i = (size_t)blockIdx.x * blockDim.x + threadIdx.x;
    if (i < (size_t)NB * NH) y[i] = 0.f;
    if (i < NE) { g_cnt[i] = 0; g_psum[i] = 0.f; g_rsum[i] = 0.f; }
}

// ---------------- fp32 -> fp16 conversion into the right scratch ----------------
template<int WHICH>
__global__ void f2h_kernel(const float* __restrict__ src, size_t n4) {
    size_t i = (size_t)blockIdx.x * blockDim.x + threadIdx.x;
    if (i >= n4) return;
    __half* dst = (WHICH == 0) ? g_xh : (WHICH == 1) ? g_w1h : g_w2h;
    float4 v = reinterpret_cast<const float4*>(src)[i];
    __half2* d2 = reinterpret_cast<__half2*>(dst) + i * 2;
    d2[0] = __floats2half2_rn(v.x, v.y);
    d2[1] = __floats2half2_rn(v.z, v.w);
}

// ---------------- gating: logits, softmax, top-2 routing, aux sums ----------------
__global__ void gate_kernel(const float* __restrict__ x,
                            const float* __restrict__ gw,
                            const float* __restrict__ gb) {
    __shared__ float sx[NH];
    __shared__ float slog[NE];
    const int b   = blockIdx.x;
    const int tid = threadIdx.x;
    for (int i = tid; i < NH; i += 256) sx[i] = x[(size_t)b * NH + i];
    __syncthreads();
    const int w = tid >> 5, lane = tid & 31;
    float s = 0.f;
    for (int i = lane; i < NH; i += 32) s += sx[i] * gw[i * NE + w];
    #pragma unroll
    for (int o = 16; o; o >>= 1) s += __shfl_xor_sync(0xffffffffu, s, o);
    if (lane == 0) slog[w] = s + gb[w];
    __syncthreads();
    if (tid == 0) {
        float p[NE];
        float mx = slog[0];
        #pragma unroll
        for (int e = 1; e < NE; e++) mx = fmaxf(mx, slog[e]);
        float den = 0.f;
        #pragma unroll
        for (int e = 0; e < NE; e++) { p[e] = expf(slog[e] - mx); den += p[e]; }
        float inv = 1.f / den;
        #pragma unroll
        for (int e = 0; e < NE; e++) p[e] *= inv;
        // top-1 (lowest index wins ties)
        int e1 = 0; float p1 = p[0];
        #pragma unroll
        for (int e = 1; e < NE; e++) if (p[e] > p1) { p1 = p[e]; e1 = e; }
        // top-2 excluding e1 (lowest index wins ties)
        int e2 = (e1 == 0) ? 1 : 0; float p2 = p[e2];
        #pragma unroll
        for (int e = 0; e < NE; e++)
            if (e != e1 && p[e] > p2) { p2 = p[e]; e2 = e; }

        int pos = atomicAdd(&g_cnt[e1], 1);
        g_idx[e1 * NB + pos] = b; g_scale[e1 * NB + pos] = p1 * 0.5f;
        pos = atomicAdd(&g_cnt[e2], 1);
        g_idx[e2 * NB + pos] = b; g_scale[e2 * NB + pos] = p2 * 0.5f;
        #pragma unroll
        for (int e = 0; e < NE; e++) atomicAdd(&g_psum[e], p[e]);
        atomicAdd(&g_rsum[e1], 1.f);
        atomicAdd(&g_rsum[e2], 1.f);
    }
}

// ---------------- grouped GEMM: 128x128x32 tiles, cp.async double buffer, m16n8k16 ----------------
// ISB == false:  h = relu(X_gathered @ w1[e] + b1[e])          (KDIM=NH, NDIM=ND)
// ISB == true :  y[token] += scale * (h @ w2[e] + b2[e])       (KDIM=ND, NDIM=NH)
template<int KDIM, int NDIM, bool ISB>
__global__ void __launch_bounds__(256)
moe_gemm_kernel(const float* __restrict__ bias, float* __restrict__ y) {
    const int e   = blockIdx.z;
    const int cnt = g_cnt[e];
    const int m0  = blockIdx.y * 128;
    if (m0 >= cnt) return;
    const int n0  = blockIdx.x * 128;

    __shared__ __half As[2][128][40];
    __shared__ __half Bs[2][32][136];

    const int tid = threadIdx.x;
    const __half* W = (ISB ? g_w2h : g_w1h) + (size_t)e * KDIM * NDIM + n0;

    // A-tile loading: 512 x 16B chunks, 2 per thread
    const int ar0 = tid >> 2, ao0 = (tid & 3) * 8;
    const int ar1 = ar0 + 64;
    const __half *Ar0, *Ar1;
    if (ISB) {
        Ar0 = g_h + ((size_t)e * NB + m0 + ar0) * ND;
        Ar1 = g_h + ((size_t)e * NB + m0 + ar1) * ND;
    } else {
        int s0 = m0 + ar0, s1 = m0 + ar1;
        int t0 = g_idx[e * NB + (s0 < cnt ? s0 : 0)];
        int t1 = g_idx[e * NB + (s1 < cnt ? s1 : 0)];
        Ar0 = g_xh + (size_t)t0 * NH;
        Ar1 = g_xh + (size_t)t1 * NH;
    }
    // B-tile loading: 512 x 16B chunks
    const int br0 = tid >> 4, bo0 = (tid & 15) * 8;
    const int br1 = br0 + 16;

    auto load = [&](int k0, int buf) {
        cp16(&As[buf][ar0][ao0], Ar0 + k0 + ao0);
        cp16(&As[buf][ar1][ao0], Ar1 + k0 + ao0);
        cp16(&Bs[buf][br0][bo0], W + (size_t)(k0 + br0) * NDIM + bo0);
        cp16(&Bs[buf][br1][bo0], W + (size_t)(k0 + br1) * NDIM + bo0);
        asm volatile("cp.async.commit_group;\n" ::: "memory");
    };

    float acc[2][8][4];
    #pragma unroll
    for (int i = 0; i < 2; i++)
        #pragma unroll
        for (int j = 0; j < 8; j++)
            #pragma unroll
            for (int q = 0; q < 4; q++) acc[i][j][q] = 0.f;

    const int lane = tid & 31, warp = tid >> 5;
    const int wm = (warp & 3) * 32, wn = (warp >> 2) * 64;

    load(0, 0);
    const int KT = KDIM / 32;
    for (int kt = 0; kt < KT; kt++) {
        if (kt + 1 < KT) {
            load((kt + 1) * 32, (kt + 1) & 1);
            asm volatile("cp.async.wait_group 1;\n" ::: "memory");
        } else {
            asm volatile("cp.async.wait_group 0;\n" ::: "memory");
        }
        __syncthreads();
        const int buf = kt & 1;
        #pragma unroll
        for (int ks = 0; ks < 2; ks++) {
            const int k16 = ks * 16;
            uint32_t a[2][4], b[4][4];
            #pragma unroll
            for (int im = 0; im < 2; im++) {
                uint32_t sa = smem_u32(&As[buf][wm + im * 16 + (lane & 15)][k16 + (lane >> 4) * 8]);
                asm volatile("ldmatrix.sync.aligned.m8n8.x4.shared.b16 {%0,%1,%2,%3}, [%4];"
                             : "=r"(a[im][0]), "=r"(a[im][1]), "=r"(a[im][2]), "=r"(a[im][3])
                             : "r"(sa));
            }
            #pragma unroll
            for (int g = 0; g < 4; g++) {
                uint32_t sb = smem_u32(&Bs[buf][k16 + (lane & 15)][wn + g * 16 + (lane >> 4) * 8]);
                asm volatile("ldmatrix.sync.aligned.m8n8.x4.trans.shared.b16 {%0,%1,%2,%3}, [%4];"
                             : "=r"(b[g][0]), "=r"(b[g][1]), "=r"(b[g][2]), "=r"(b[g][3])
                             : "r"(sb));
            }
            #pragma unroll
            for (int im = 0; im < 2; im++)
                #pragma unroll
                for (int jn = 0; jn < 8; jn++) {
                    const uint32_t b0 = b[jn >> 1][(jn & 1) * 2 + 0];
                    const uint32_t b1 = b[jn >> 1][(jn & 1) * 2 + 1];
                    asm volatile("mma.sync.aligned.m16n8k16.row.col.f32.f16.f16.f32 "
                                 "{%0,%1,%2,%3},{%4,%5,%6,%7},{%8,%9},{%0,%1,%2,%3};"
                                 : "+f"(acc[im][jn][0]), "+f"(acc[im][jn][1]),
                                   "+f"(acc[im][jn][2]), "+f"(acc[im][jn][3])
                                 : "r"(a[im][0]), "r"(a[im][1]), "r"(a[im][2]), "r"(a[im][3]),
                                   "r"(b0), "r"(b1));
                }
        }
        __syncthreads();
    }

    // epilogue
    const int rb = lane >> 2;
    const int cb = (lane & 3) * 2;
    #pragma unroll
    for (int im = 0; im < 2; im++) {
        #pragma unroll
        for (int h = 0; h < 2; h++) {
            const int row = wm + im * 16 + rb + h * 8;
            if (!ISB) {
                const size_t hbase = ((size_t)e * NB + m0 + row) * ND;
                #pragma unroll
                for (int jn = 0; jn < 8; jn++) {
                    const int gc = n0 + wn + jn * 8 + cb;
                    float v0 = fmaxf(acc[im][jn][h * 2 + 0] + bias[e * NDIM + gc], 0.f);
                    float v1 = fmaxf(acc[im][jn][h * 2 + 1] + bias[e * NDIM + gc + 1], 0.f);
                    *reinterpret_cast<__half2*>(&g_h[hbase + gc]) = __floats2half2_rn(v0, v1);
                }
            } else {
                const int slot = m0 + row;
                if (slot < cnt) {
                    const int   token = g_idx[e * NB + slot];
                    const float sc    = g_scale[e * NB + slot];
                    float* yrow = y + (size_t)token * NH;
                    #pragma unroll
                    for (int jn = 0; jn < 8; jn++) {
                        const int gc = n0 + wn + jn * 8 + cb;
                        float v0 = (acc[im][jn][h * 2 + 0] + bias[e * NDIM + gc]) * sc;
                        float v1 = (acc[im][jn][h * 2 + 1] + bias[e * NDIM + gc + 1]) * sc;
                        atomicAdd(&yrow[gc],     v0);
                        atomicAdd(&yrow[gc + 1], v1);
                    }
                }
            }
        }
    }
}

// ---------------- aux loss ----------------
__global__ void aux_kernel(float* __restrict__ out) {
    float s = 0.f;
    #pragma unroll
    for (int e = 0; e < NE; e++)
        s += (g_psum[e] / (float)NB) * (g_rsum[e] / (float)NB);
    out[(size_t)NB * NH] = s * (float)NE;
}

// ---------------- launch ----------------
extern "C" void kernel_launch(void* const* d_in, const int* in_sizes, int n_in,
                              void* d_out, int out_size) {
    const float* x  = (const float*)d_in[0];
    const float* gw = (const float*)d_in[1];
    const float* gb = (const float*)d_in[2];
    const float* w1 = (const float*)d_in[3];
    const float* b1 = (const float*)d_in[4];
    const float* w2 = (const float*)d_in[5];
    const float* b2 = (const float*)d_in[6];
    float* y = (float*)d_out;

    const size_t nx  = (size_t)NB * NH / 4;
    const size_t nw1 = (size_t)NE * NH * ND / 4;
    const size_t nw2 = (size_t)NE * ND * NH / 4;

    init_kernel<<<(NB * NH + 255) / 256, 256>>>(y);
    f2h_kernel<0><<<(unsigned)((nx  + 255) / 256), 256>>>(x,  nx);
    f2h_kernel<1><<<(unsigned)((nw1 + 255) / 256), 256>>>(w1, nw1);
    f2h_kernel<2><<<(unsigned)((nw2 + 255) / 256), 256>>>(w2, nw2);
    gate_kernel<<<NB, 256>>>(x, gw, gb);
    moe_gemm_kernel<NH, ND, false><<<dim3(ND / 128, NB / 128, NE), 256>>>(b1, nullptr);
    moe_gemm_kernel<ND, NH, true ><<<dim3(NH / 128, NB / 128, NE), 256>>>(b2, y);
    aux_kernel<<<1, 1>>>(y);
}